// round 5
// baseline (speedup 1.0000x reference)
#include <cuda_runtime.h>
#include <cuda_fp16.h>
#include <cstdint>

// Problem constants (fixed by setup_inputs): B=8, C=1, H=352, W=1216, times=24
#define Bn 8
#define Hn 352
#define Wn 1216
#define HW (Hn * Wn)            // 428032
#define BHW (Bn * HW)           // 3424256
#define TIMES 24
#define NGROUPS 2               // batch split: keep per-group WS (~42 MB) L2-resident
#define BG (Bn / NGROUPS)

// Padded feature layout: stride 1248, 16 guard cols each side, 3 guard rows
// top/bottom (halo-3 for fusion). Guard cells are ALWAYS zero.
#define PSTR 1248
#define GROW 3
#define PIMG ((Hn + 2 * GROW) * PSTR)   // 358*1248 per image
#define COFF 16

// Temporal fusion: 3 steps per kernel, output tile 152x16.
#define FUSE 3
#define TW 152                  // 1216/152 = 8 tiles
#define TH 16                   // 352/16  = 22 tiles
#define SW (TW + 2 * FUSE)      // 158
#define SH (TH + 2 * FUSE)      // 22
#define SP 160                  // smem pitch (floats)

// Static device scratch (allocation-free).
__device__ uint4    g_affp[BHW];                    // 8 fp16 weights per pixel
__device__ float    g_feat0[(size_t)Bn * PIMG];
__device__ float    g_feat1[(size_t)Bn * PIMG];
__device__ unsigned g_mask[BHW / 32];

// ---------------------------------------------------------------------------
// Zero both padded feature buffers entirely (guards stay zero forever;
// interior is overwritten by prep / step kernels).
// ---------------------------------------------------------------------------
__global__ void zero_kernel()
{
    const size_t n = (size_t)Bn * PIMG;
    for (size_t i = blockIdx.x * (size_t)blockDim.x + threadIdx.x; i < n;
         i += (size_t)gridDim.x * blockDim.x) {
        g_feat0[i] = 0.0f;
        g_feat1[i] = 0.0f;
    }
}

// ---------------------------------------------------------------------------
// Prep: normalize |affinity|, pack the 8 non-center weights as fp16 into one
// uint4 per pixel; build initial padded feature and the validity bitmask.
// ---------------------------------------------------------------------------
__global__ void prep_kernel(const float* __restrict__ aff,
                            const float* __restrict__ feature,
                            const float* __restrict__ sparse)
{
    const int w  = blockIdx.x * 32 + threadIdx.x;   // W = 38*32 exact
    const int h  = blockIdx.y * 8  + threadIdx.y;   // H = 44*8 exact
    const int b  = blockIdx.z;
    const int hw = h * Wn + w;
    const size_t idx = (size_t)b * HW + hw;

    const float* ap = aff + (size_t)b * 9 * HW + hw;
    float a[9];
    float s = 0.0f;
#pragma unroll
    for (int k = 0; k < 9; ++k) {
        a[k] = fabsf(__ldg(ap + (size_t)k * HW));
        s += a[k];
    }
    const float inv = 1.0f / s;

    // taps in step order: (-1,-1)(-1,0)(-1,+1)(0,-1)(0,+1)(+1,-1)(+1,0)(+1,+1)
    __half2 h01 = __floats2half2_rn(a[0] * inv, a[1] * inv);
    __half2 h23 = __floats2half2_rn(a[2] * inv, a[3] * inv);
    __half2 h56 = __floats2half2_rn(a[5] * inv, a[6] * inv);
    __half2 h78 = __floats2half2_rn(a[7] * inv, a[8] * inv);
    uint4 wv;
    wv.x = *reinterpret_cast<unsigned*>(&h01);
    wv.y = *reinterpret_cast<unsigned*>(&h23);
    wv.z = *reinterpret_cast<unsigned*>(&h56);
    wv.w = *reinterpret_cast<unsigned*>(&h78);
    g_affp[idx] = wv;

    const float sd = __ldg(sparse + idx);
    const bool  m  = sd > 0.0f;
    const size_t pidx = (size_t)b * PIMG + (size_t)(h + GROW) * PSTR + (w + COFF);
    g_feat0[pidx] = m ? sd : __ldg(feature + idx);

    const unsigned bal = __ballot_sync(0xFFFFFFFFu, m);
    if (threadIdx.x == 0) g_mask[idx >> 5] = bal;   // bit index == w&31 (Wn%32==0)
}

// ---------------------------------------------------------------------------
// Fused 3-step propagation. Loads a (TW+6)x(TH+6) tile into smem, runs 3
// Jacobi steps on shrinking rings (aff/mask re-read from global; L1-hot after
// step 0), writes the final tile to global (padded scratch or unpadded d_out).
// Ring cells outside the image are written as literal zeros, reproducing the
// reference's per-step zero padding.
// ---------------------------------------------------------------------------
__global__ void __launch_bounds__(256)
fused_kernel(const float* __restrict__ fin,
             float* __restrict__ fout,
             int bBase, int lastFlag)
{
    __shared__ float sA[SH][SP];
    __shared__ float sB[SH][SP];

    const int tx = threadIdx.x & 31;
    const int ty = threadIdx.x >> 5;
    const int gx0 = blockIdx.x * TW;
    const int gy0 = blockIdx.y * TH;
    const int b   = bBase + blockIdx.z;

    // Initial load with halo 3: smem (sy,sx) <-> image (gy0+sy-3, gx0+sx-3).
    // Padded global indices are always in-bounds (guards >= 3 cells).
    const float* fb = fin + (size_t)b * PIMG;
#pragma unroll
    for (int sy = ty; sy < SH; sy += 8) {
        for (int sx = tx; sx < SW; sx += 32) {
            const float v = __ldg(fb + (size_t)(gy0 + sy) * PSTR + (COFF - FUSE) + gx0 + sx);
            sA[sy][sx] = v;
            sB[sy][sx] = v;   // both buffers: out-of-image cells must be 0 in both
        }
    }
    __syncthreads();

#pragma unroll
    for (int s = 0; s < FUSE; ++s) {
        const int m = (FUSE - 1) - s;               // ring margin: 2,1,0
        float (*rb)[SP] = (s & 1) ? sB : sA;
        float (*wb)[SP] = (s & 1) ? sA : sB;

        for (int ry = -m + ty; ry < TH + m; ry += 8) {
            for (int rx = -m + tx; rx < TW + m; rx += 32) {
                const int gy = gy0 + ry;
                const int gx = gx0 + rx;
                const int sy = ry + FUSE;
                const int sx = rx + FUSE;
                const float fc = rb[sy][sx];
                float v = 0.0f;
                if (((unsigned)gy < (unsigned)Hn) && ((unsigned)gx < (unsigned)Wn)) {
                    const size_t idx = (size_t)b * HW + (size_t)gy * Wn + gx;
                    const uint4 wv = __ldg(&g_affp[idx]);
                    const __half2* hp = reinterpret_cast<const __half2*>(&wv);
                    const float2 p0 = __half22float2(hp[0]);
                    const float2 p1 = __half22float2(hp[1]);
                    const float2 p2 = __half22float2(hp[2]);
                    const float2 p3 = __half22float2(hp[3]);

                    float out = fc;
                    out = fmaf(p0.x, rb[sy - 1][sx - 1] - fc, out);
                    out = fmaf(p0.y, rb[sy - 1][sx    ] - fc, out);
                    out = fmaf(p1.x, rb[sy - 1][sx + 1] - fc, out);
                    out = fmaf(p1.y, rb[sy    ][sx - 1] - fc, out);
                    out = fmaf(p2.x, rb[sy    ][sx + 1] - fc, out);
                    out = fmaf(p2.y, rb[sy + 1][sx - 1] - fc, out);
                    out = fmaf(p3.x, rb[sy + 1][sx    ] - fc, out);
                    out = fmaf(p3.y, rb[sy + 1][sx + 1] - fc, out);

                    const unsigned mw = __ldg(&g_mask[idx >> 5]);
                    const bool mk = (mw >> (gx & 31)) & 1u;
                    v = mk ? fc : out;
                }
                if (s < FUSE - 1) {
                    wb[sy][sx] = v;
                } else {
                    // final ring is exactly the tile: always in-image
                    if (lastFlag) {
                        fout[(size_t)b * HW + (size_t)gy * Wn + gx] = v;
                    } else {
                        fout[(size_t)b * PIMG + (size_t)(gy + GROW) * PSTR + COFF + gx] = v;
                    }
                }
            }
        }
        if (s < FUSE - 1) __syncthreads();
    }
}

// ---------------------------------------------------------------------------
extern "C" void kernel_launch(void* const* d_in, const int* in_sizes, int n_in,
                              void* d_out, int out_size)
{
    const float* aff     = (const float*)d_in[0];
    const float* feature = (const float*)d_in[1];
    const float* sparse  = (const float*)d_in[2];
    float* out = (float*)d_out;

    float* f0 = nullptr;
    float* f1 = nullptr;
    cudaGetSymbolAddress((void**)&f0, g_feat0);
    cudaGetSymbolAddress((void**)&f1, g_feat1);

    const dim3 blk(32, 8);
    const dim3 grdAll(Wn / 32, Hn / 8, Bn);
    const dim3 grdFused(Wn / TW, Hn / TH, BG);      // (8, 22, 4)

    zero_kernel<<<2048, 256>>>();
    prep_kernel<<<grdAll, blk>>>(aff, feature, sparse);

    const int NFUSED = TIMES / FUSE;                // 8 fused launches per group
    for (int g = 0; g < NGROUPS; ++g) {
        const int bBase = g * BG;
        for (int j = 0; j < NFUSED; ++j) {
            const float* fin = (j & 1) ? f1 : f0;
            float*       fo  = (j & 1) ? f0 : f1;
            const int last = (j == NFUSED - 1);
            fused_kernel<<<grdFused, 256>>>(fin, last ? out : fo, bBase, last);
        }
    }
}